// round 11
// baseline (speedup 1.0000x reference)
#include <cuda_runtime.h>
#include <cstdint>

#define B_   256
#define T_   2048
#define IN_  128
#define H_   64
#define G_   256   // 4*H

// Scratch (allocation-free rule: static __device__ array)
__device__ float g_xp[(size_t)B_ * T_ * G_];   // precomputed x@W_ih1^T + b_ih1 + b_hh1

typedef unsigned long long u64;

// ---------------- helpers ----------------
__device__ __forceinline__ void ffma2(u64& d, u64 a, u64 b) {
    asm("fma.rn.f32x2 %0, %1, %2, %0;" : "+l"(d) : "l"(a), "l"(b));
}
__device__ __forceinline__ float2 unpk(u64 p) {
    float2 r;
    asm("mov.b64 {%0, %1}, %2;" : "=f"(r.x), "=f"(r.y) : "l"(p));
    return r;
}
__device__ __forceinline__ float sigf(float x) {
    return __fdividef(1.0f, 1.0f + __expf(-x));
}
__device__ __forceinline__ float tanhf_(float x) {
    float a = fabsf(x);
    float e = __expf(2.0f * a);                 // inf-safe
    float r = 1.0f - __fdividef(2.0f, e + 1.0f);
    return copysignf(r, x);
}

// ---------------- kernel 1: xp = x @ W_ih1^T + b_ih1 + b_hh1 ----------------
// (unchanged from R8 — W tile staged in smem, broadcast LDG.128 for x)
__global__ __launch_bounds__(256) void xp_gemm(const float* __restrict__ x,
                                               const float* __restrict__ W,
                                               const float* __restrict__ bih,
                                               const float* __restrict__ bhh) {
    __shared__ float Ws[64][132];              // 33 KB
    int tid = threadIdx.x;
    size_t mbase = (size_t)blockIdx.x * 64;
    int nbase = blockIdx.y * 64;

#pragma unroll
    for (int i = 0; i < 8; i++) {
        int idx = tid + i * 256;
        int r = idx >> 5, c4 = (idx & 31) << 2;
        *(float4*)&Ws[r][c4] = *(const float4*)(W + (size_t)(nbase + r) * IN_ + c4);
    }
    __syncthreads();

    int tx = tid & 15, ty = tid >> 4;
    int m0 = ty * 4;
    const float* xg = x + (mbase + m0) * IN_;

    u64 acc[4][4];
#pragma unroll
    for (int i = 0; i < 4; i++)
#pragma unroll
        for (int j = 0; j < 4; j++) acc[i][j] = 0ull;

#pragma unroll 4
    for (int k4 = 0; k4 < IN_; k4 += 4) {
        u64 wv[4][2];
#pragma unroll
        for (int j = 0; j < 4; j++) {
            ulonglong2 t2 = *(const ulonglong2*)&Ws[tx + 16 * j][k4];
            wv[j][0] = t2.x; wv[j][1] = t2.y;
        }
#pragma unroll
        for (int i = 0; i < 4; i++) {
            ulonglong2 xv = *(const ulonglong2*)(xg + (size_t)i * IN_ + k4);
#pragma unroll
            for (int j = 0; j < 4; j++) {
                ffma2(acc[i][j], xv.x, wv[j][0]);
                ffma2(acc[i][j], xv.y, wv[j][1]);
            }
        }
    }

#pragma unroll
    for (int j = 0; j < 4; j++) {
        int n = nbase + tx + 16 * j;
        float b = bih[n] + bhh[n];
#pragma unroll
        for (int i = 0; i < 4; i++) {
            float2 p = unpk(acc[i][j]);
            g_xp[(mbase + m0 + i) * G_ + n] = p.x + p.y + b;
        }
    }
}

// ---------------- kernel 2: fused 2-layer LSTM recurrence + output head ----------------
// 128 CTAs x 256 threads, 2 batch rows per CTA.
// Thread (q = tid>>2: unit; s = tid&3: k-split); gate-interleaved weight rows.
// SINGLE BARRIER PER STEP. Loop carries wv1(t) and wv2(t-1) (reduced gate sums).
//   top(t):  cell2(t-1) -> store h2s[prv-par], head partials -> red[prv-par]
//            cell1(t)   -> store h1s[par];   prefetch xp(t+1)
//   BARRIER
//   post(t): fused dots: a = W2h*h2(t-1) + W2i*h1(t)  (-> wv2(t))
//                        b = W1 *h1(t)               (-> wv1(t+1))
//            reduces; lagged out(t-1) from red[prv-par]
// All row selects removed: per-thread pointers are swapped once by myrow so
// acc[2g+0] is always "my row".
__global__ __launch_bounds__(256, 1) void lstm_rec(
    const float* __restrict__ Whh1, const float* __restrict__ Wih2,
    const float* __restrict__ Whh2, const float* __restrict__ bih2,
    const float* __restrict__ bhh2, const float* __restrict__ Wout,
    const float* __restrict__ bout, float* __restrict__ out) {
    __shared__ float h1s[2][2][64];   // [parity][row][unit]
    __shared__ float h2s[2][2][64];
    __shared__ float red[2][16];      // [parity][warp*2+row]

    int tid = threadIdx.x;
    int q = tid >> 2, s = tid & 3;
    int myrow = s & 1;

    // ---- weights into registers (gate-interleaved rows, k in [16s,16s+16)) ----
    u64 w1[4][8], w2i[4][8], w2h[4][8];
#pragma unroll
    for (int g = 0; g < 4; g++) {
        const u64* p;
        p = (const u64*)(Whh1 + (size_t)(g * 64 + q) * 64 + s * 16);
#pragma unroll
        for (int j = 0; j < 8; j++) w1[g][j] = p[j];
        p = (const u64*)(Wih2 + (size_t)(g * 64 + q) * 64 + s * 16);
#pragma unroll
        for (int j = 0; j < 8; j++) w2i[g][j] = p[j];
        p = (const u64*)(Whh2 + (size_t)(g * 64 + q) * 64 + s * 16);
#pragma unroll
        for (int j = 0; j < 8; j++) w2h[g][j] = p[j];
    }
    float b2v = bih2[s * 64 + q] + bhh2[s * 64 + q];   // bias of gate s*64+q
    float wo = Wout[q];
    float bo = bout[0];
    float c1 = 0.0f, c2 = 0.0f;                        // carries for row = myrow

    int b0 = blockIdx.x * 2;
    // xp pointers swapped so xqo is always "my row", xqp the partner's
    const float* xprow0 = g_xp + (size_t)b0 * T_ * G_ + s * 64 + q;
    const float* xprow1 = xprow0 + (size_t)T_ * G_;
    const float* xpo = myrow ? xprow1 : xprow0;
    const float* xpp = myrow ? xprow0 : xprow1;
    float xqo = xpo[0];
    float xqp = xpp[0];

    __syncthreads();   // weights/h init ordering (h buffers written below pre-use)

    // ---- prologue: wv1(0) (h=0 so layer-1 gates(0) = xp(0) distributed) ----
    float wv1[4], wv2[4];
#pragma unroll
    for (int g = 0; g < 4; g++) {
        float fo = (s == g) ? xqo : 0.0f;
        float fp = (s == g) ? xqp : 0.0f;
        float tt = fo + __shfl_xor_sync(0xffffffffu, fp, 1);
        tt += __shfl_xor_sync(0xffffffffu, tt, 2);
        wv1[g] = tt;
        wv2[g] = 0.0f;                 // unused at t=0
    }

    for (int t = 0; t < T_; t++) {
        int par = t & 1, prv = par ^ 1;

        // ---- TOP: cell2(t-1) ----
        float h2v;
        if (t > 0) {
            float iv = sigf(wv2[0]), fv = sigf(wv2[1]);
            float gv = tanhf_(wv2[2]), ov = sigf(wv2[3]);
            c2 = fv * c2 + iv * gv;
            h2v = ov * tanhf_(c2);
        } else {
            h2v = 0.0f;
        }
        if (s < 2) h2s[prv][s][q] = h2v;   // h2(t-1) in parity prv
        {   // head partials for out(t-1)
            float p = wo * h2v;
            p += __shfl_xor_sync(0xffffffffu, p, 4);
            p += __shfl_xor_sync(0xffffffffu, p, 8);
            p += __shfl_xor_sync(0xffffffffu, p, 16);
            if ((tid & 31) < 2) red[prv][(tid >> 5) * 2 + s] = p;
        }

        // ---- TOP: cell1(t) ----
        {
            float iv = sigf(wv1[0]), fv = sigf(wv1[1]);
            float gv = tanhf_(wv1[2]), ov = sigf(wv1[3]);
            c1 = fv * c1 + iv * gv;
            float h1v = ov * tanhf_(c1);
            if (s < 2) h1s[par][s][q] = h1v;   // h1(t) in parity par
        }

        // prefetch xp(t+1)
        if (t + 1 < T_) {
            xqo = xpo[(size_t)(t + 1) * G_];
            xqp = xpp[(size_t)(t + 1) * G_];
        }
        __syncthreads();               // THE barrier

        // ---- POST: fused dots.  own-row pointers (no selects) ----
        u64 a[8], b[8];                // [2g+0]=own row, [2g+1]=partner row
#pragma unroll
        for (int i = 0; i < 8; i++) { a[i] = 0ull; b[i] = 0ull; }
        {
            const ulonglong2* h2o = (const ulonglong2*)&h2s[prv][myrow][s * 16];
            const ulonglong2* h2p = (const ulonglong2*)&h2s[prv][myrow ^ 1][s * 16];
            const ulonglong2* h1o = (const ulonglong2*)&h1s[par][myrow][s * 16];
            const ulonglong2* h1p = (const ulonglong2*)&h1s[par][myrow ^ 1][s * 16];
#pragma unroll
            for (int j = 0; j < 4; j++) {
                ulonglong2 z0 = h2o[j];
                ulonglong2 z1 = h2p[j];
#pragma unroll
                for (int g = 0; g < 4; g++) {
                    ffma2(a[2 * g + 0], w2h[g][2 * j], z0.x);
                    ffma2(a[2 * g + 0], w2h[g][2 * j + 1], z0.y);
                    ffma2(a[2 * g + 1], w2h[g][2 * j], z1.x);
                    ffma2(a[2 * g + 1], w2h[g][2 * j + 1], z1.y);
                }
                ulonglong2 u0 = h1o[j];
                ulonglong2 u1 = h1p[j];
#pragma unroll
                for (int g = 0; g < 4; g++) {
                    ffma2(a[2 * g + 0], w2i[g][2 * j], u0.x);
                    ffma2(a[2 * g + 0], w2i[g][2 * j + 1], u0.y);
                    ffma2(a[2 * g + 1], w2i[g][2 * j], u1.x);
                    ffma2(a[2 * g + 1], w2i[g][2 * j + 1], u1.y);
                }
#pragma unroll
                for (int g = 0; g < 4; g++) {
                    ffma2(b[2 * g + 0], w1[g][2 * j], u0.x);
                    ffma2(b[2 * g + 0], w1[g][2 * j + 1], u0.y);
                    ffma2(b[2 * g + 1], w1[g][2 * j], u1.x);
                    ffma2(b[2 * g + 1], w1[g][2 * j + 1], u1.y);
                }
            }
        }

        // ---- reduce a -> wv2(t)  (bias folded from lane s==g only) ----
#pragma unroll
        for (int g = 0; g < 4; g++) {
            float bb = (s == g) ? b2v : 0.0f;
            float2 fo = unpk(a[2 * g + 0]);
            float2 fp = unpk(a[2 * g + 1]);
            float vo = fo.x + fo.y + bb;
            float vp = fp.x + fp.y + bb;
            float tt = vo + __shfl_xor_sync(0xffffffffu, vp, 1);
            tt += __shfl_xor_sync(0xffffffffu, tt, 2);
            wv2[g] = tt;
        }

        // ---- reduce b -> wv1(t+1)  (xp(t+1) folded from lane s==g) ----
#pragma unroll
        for (int g = 0; g < 4; g++) {
            float2 fo = unpk(b[2 * g + 0]);
            float2 fp = unpk(b[2 * g + 1]);
            float vo = fo.x + fo.y + ((s == g) ? xqo : 0.0f);
            float vp = fp.x + fp.y + ((s == g) ? xqp : 0.0f);
            float tt = vo + __shfl_xor_sync(0xffffffffu, vp, 1);
            tt += __shfl_xor_sync(0xffffffffu, tt, 2);
            wv1[g] = tt;
        }

        // ---- lagged output write: out(t-1) ----
        if (t > 0 && tid < 2) {
            float r = bo;
#pragma unroll
            for (int w = 0; w < 8; w++) r += red[prv][w * 2 + tid];
            r = fminf(fmaxf(r, 0.0f), 1.0f);
            out[(size_t)(b0 + tid) * T_ + (t - 1)] = r;
        }
    }

    // ---- epilogue: cell2(T-1) + out(T-1) ----
    {
        float iv = sigf(wv2[0]), fv = sigf(wv2[1]);
        float gv = tanhf_(wv2[2]), ov = sigf(wv2[3]);
        c2 = fv * c2 + iv * gv;
        float h2v = ov * tanhf_(c2);
        float p = wo * h2v;
        p += __shfl_xor_sync(0xffffffffu, p, 4);
        p += __shfl_xor_sync(0xffffffffu, p, 8);
        p += __shfl_xor_sync(0xffffffffu, p, 16);
        if ((tid & 31) < 2) red[0][(tid >> 5) * 2 + s] = p;
    }
    __syncthreads();
    if (tid < 2) {
        float r = bo;
#pragma unroll
        for (int w = 0; w < 8; w++) r += red[0][w * 2 + tid];
        r = fminf(fmaxf(r, 0.0f), 1.0f);
        out[(size_t)(b0 + tid) * T_ + (T_ - 1)] = r;
    }
}

// ---------------- launch ----------------
extern "C" void kernel_launch(void* const* d_in, const int* in_sizes, int n_in,
                              void* d_out, int out_size) {
    const float* x    = (const float*)d_in[0];
    const float* Wih1 = (const float*)d_in[1];
    const float* Whh1 = (const float*)d_in[2];
    const float* bih1 = (const float*)d_in[3];
    const float* bhh1 = (const float*)d_in[4];
    const float* Wih2 = (const float*)d_in[5];
    const float* Whh2 = (const float*)d_in[6];
    const float* bih2 = (const float*)d_in[7];
    const float* bhh2 = (const float*)d_in[8];
    const float* Wout = (const float*)d_in[9];
    const float* bout = (const float*)d_in[10];
    float* out = (float*)d_out;

    xp_gemm<<<dim3((B_ * T_) / 64, G_ / 64), 256>>>(x, Wih1, bih1, bhh1);
    lstm_rec<<<128, 256>>>(Whh1, Wih2, Whh2, bih2, bhh2, Wout, bout, out);
    (void)in_sizes; (void)n_in; (void)out_size;
}

// round 12
// speedup vs baseline: 1.1299x; 1.1299x over previous
#include <cuda_runtime.h>
#include <cstdint>

#define B_   256
#define T_   2048
#define IN_  128
#define H_   64
#define G_   256   // 4*H

// Scratch (allocation-free rule: static __device__ array)
__device__ float g_xp[(size_t)B_ * T_ * G_];   // precomputed x@W_ih1^T + b_ih1 + b_hh1

typedef unsigned long long u64;

// ---------------- helpers ----------------
__device__ __forceinline__ void ffma2(u64& d, u64 a, u64 b) {
    asm("fma.rn.f32x2 %0, %1, %2, %0;" : "+l"(d) : "l"(a), "l"(b));
}
__device__ __forceinline__ float2 unpk(u64 p) {
    float2 r;
    asm("mov.b64 {%0, %1}, %2;" : "=f"(r.x), "=f"(r.y) : "l"(p));
    return r;
}
__device__ __forceinline__ float tanh_hw(float x) {
    float r;
    asm("tanh.approx.f32 %0, %1;" : "=f"(r) : "f"(x));
    return r;
}
__device__ __forceinline__ float sig_hw(float x) {
    return fmaf(0.5f, tanh_hw(0.5f * x), 0.5f);
}

// ---------------- kernel 1: xp = x @ W_ih1^T + b_ih1 + b_hh1 ----------------
// (unchanged from R8 — W tile staged in smem, broadcast LDG.128 for x)
__global__ __launch_bounds__(256) void xp_gemm(const float* __restrict__ x,
                                               const float* __restrict__ W,
                                               const float* __restrict__ bih,
                                               const float* __restrict__ bhh) {
    __shared__ float Ws[64][132];              // 33 KB
    int tid = threadIdx.x;
    size_t mbase = (size_t)blockIdx.x * 64;
    int nbase = blockIdx.y * 64;

#pragma unroll
    for (int i = 0; i < 8; i++) {
        int idx = tid + i * 256;
        int r = idx >> 5, c4 = (idx & 31) << 2;
        *(float4*)&Ws[r][c4] = *(const float4*)(W + (size_t)(nbase + r) * IN_ + c4);
    }
    __syncthreads();

    int tx = tid & 15, ty = tid >> 4;
    int m0 = ty * 4;
    const float* xg = x + (mbase + m0) * IN_;

    u64 acc[4][4];
#pragma unroll
    for (int i = 0; i < 4; i++)
#pragma unroll
        for (int j = 0; j < 4; j++) acc[i][j] = 0ull;

#pragma unroll 4
    for (int k4 = 0; k4 < IN_; k4 += 4) {
        u64 wv[4][2];
#pragma unroll
        for (int j = 0; j < 4; j++) {
            ulonglong2 t2 = *(const ulonglong2*)&Ws[tx + 16 * j][k4];
            wv[j][0] = t2.x; wv[j][1] = t2.y;
        }
#pragma unroll
        for (int i = 0; i < 4; i++) {
            ulonglong2 xv = *(const ulonglong2*)(xg + (size_t)i * IN_ + k4);
#pragma unroll
            for (int j = 0; j < 4; j++) {
                ffma2(acc[i][j], xv.x, wv[j][0]);
                ffma2(acc[i][j], xv.y, wv[j][1]);
            }
        }
    }

#pragma unroll
    for (int j = 0; j < 4; j++) {
        int n = nbase + tx + 16 * j;
        float b = bih[n] + bhh[n];
#pragma unroll
        for (int i = 0; i < 4; i++) {
            float2 p = unpk(acc[i][j]);
            g_xp[(mbase + m0 + i) * G_ + n] = p.x + p.y + b;
        }
    }
}

// ---------------- kernel 2: fused 2-layer LSTM recurrence + output head ----------------
// R10 structure (2 barriers/step, fused P2b+P1(t+1) pass) + HW tanh activations
// + pointer-increment xp addressing.
__global__ __launch_bounds__(256, 1) void lstm_rec(
    const float* __restrict__ Whh1, const float* __restrict__ Wih2,
    const float* __restrict__ Whh2, const float* __restrict__ bih2,
    const float* __restrict__ bhh2, const float* __restrict__ Wout,
    const float* __restrict__ bout, float* __restrict__ out) {
    __shared__ float h1s[2][2][64];   // [parity][row][unit]
    __shared__ float h2s[2][2][64];
    __shared__ float red[16];         // [warp][row]

    int tid = threadIdx.x;
    int q = tid >> 2, s = tid & 3;
    int myrow = s & 1;

    // ---- weights into registers (gate-interleaved rows, k in [16s,16s+16)) ----
    u64 w1[4][8], w2i[4][8], w2h[4][8];
#pragma unroll
    for (int g = 0; g < 4; g++) {
        const u64* p;
        p = (const u64*)(Whh1 + (size_t)(g * 64 + q) * 64 + s * 16);
#pragma unroll
        for (int j = 0; j < 8; j++) w1[g][j] = p[j];
        p = (const u64*)(Wih2 + (size_t)(g * 64 + q) * 64 + s * 16);
#pragma unroll
        for (int j = 0; j < 8; j++) w2i[g][j] = p[j];
        p = (const u64*)(Whh2 + (size_t)(g * 64 + q) * 64 + s * 16);
#pragma unroll
        for (int j = 0; j < 8; j++) w2h[g][j] = p[j];
    }
    float b2v = bih2[s * 64 + q] + bhh2[s * 64 + q];   // bias of gate s*64+q
    float wo = Wout[q];
    float bo = bout[0];
    float c1 = 0.0f, c2 = 0.0f;                        // carries for row = myrow

    int b0 = blockIdx.x * 2;
    const float* xp0 = g_xp + (size_t)b0 * T_ * G_ + s * 64 + q;   // gate s*64+q
    const float* xp1 = xp0 + (size_t)T_ * G_;
    float xq0 = xp0[0];
    float xq1 = xp1[0];

    if (tid < 128) {                  // zero parity-1 (prv at t=0)
        h1s[1][tid >> 6][tid & 63] = 0.0f;
        h2s[1][tid >> 6][tid & 63] = 0.0f;
    }
    __syncthreads();

    // ---- prologue: wv1(0). h = 0 so layer-1 gates(0) = xp(0) distributed ----
    float wv1[4];
#pragma unroll
    for (int g = 0; g < 4; g++) {
        float f0 = (s == g) ? xq0 : 0.0f;   // row 0 partial
        float f1 = (s == g) ? xq1 : 0.0f;   // row 1 partial
        float snd = myrow ? f0 : f1;
        float own = myrow ? f1 : f0;
        float tt = own + __shfl_xor_sync(0xffffffffu, snd, 1);
        tt += __shfl_xor_sync(0xffffffffu, tt, 2);
        wv1[g] = tt;
    }

    for (int t = 0; t < T_; t++) {
        int cur = t & 1, prv = cur ^ 1;

        // ---- cell-1 update from carried wv1 ----
        float h1v;
        {
            float iv = sig_hw(wv1[0]), fv = sig_hw(wv1[1]);
            float gv = tanh_hw(wv1[2]), ov = sig_hw(wv1[3]);
            c1 = fv * c1 + iv * gv;
            h1v = ov * tanh_hw(c1);
        }

        // ---- P2a: layer-2 dots over h2 PREV (fills cell-1 MUFU shadow) ----
        u64 a[8];   // [2*gate + row]
#pragma unroll
        for (int i = 0; i < 8; i++) a[i] = 0ull;
        {
            const ulonglong2* hA = (const ulonglong2*)&h2s[prv][0][s * 16];
            const ulonglong2* hB = (const ulonglong2*)&h2s[prv][1][s * 16];
#pragma unroll
            for (int j = 0; j < 4; j++) {
                ulonglong2 u0 = hA[j];
                ulonglong2 u1 = hB[j];
#pragma unroll
                for (int g = 0; g < 4; g++) {
                    ffma2(a[2 * g + 0], w2h[g][2 * j], u0.x);
                    ffma2(a[2 * g + 0], w2h[g][2 * j + 1], u0.y);
                    ffma2(a[2 * g + 1], w2h[g][2 * j], u1.x);
                    ffma2(a[2 * g + 1], w2h[g][2 * j + 1], u1.y);
                }
            }
        }
        // prefetch xp(t+1) via pointer increments
        if (t + 1 < T_) {
            xp0 += G_; xp1 += G_;
            xq0 = *xp0;
            xq1 = *xp1;
        }
        if (s < 2) h1s[cur][s][q] = h1v;
        __syncthreads();              // B1: h1(cur) visible

        // ---- fused pass over h1 NEW: P2b (into a) + P1(t+1) (into b) ----
        u64 b[8];
#pragma unroll
        for (int i = 0; i < 8; i++) b[i] = 0ull;
        {
            const ulonglong2* hA = (const ulonglong2*)&h1s[cur][0][s * 16];
            const ulonglong2* hB = (const ulonglong2*)&h1s[cur][1][s * 16];
#pragma unroll
            for (int j = 0; j < 4; j++) {
                ulonglong2 u0 = hA[j];
                ulonglong2 u1 = hB[j];
#pragma unroll
                for (int g = 0; g < 4; g++) {
                    ffma2(a[2 * g + 0], w2i[g][2 * j], u0.x);
                    ffma2(a[2 * g + 0], w2i[g][2 * j + 1], u0.y);
                    ffma2(a[2 * g + 1], w2i[g][2 * j], u1.x);
                    ffma2(a[2 * g + 1], w2i[g][2 * j + 1], u1.y);
                }
#pragma unroll
                for (int g = 0; g < 4; g++) {
                    ffma2(b[2 * g + 0], w1[g][2 * j], u0.x);
                    ffma2(b[2 * g + 0], w1[g][2 * j + 1], u0.y);
                    ffma2(b[2 * g + 1], w1[g][2 * j], u1.x);
                    ffma2(b[2 * g + 1], w1[g][2 * j + 1], u1.y);
                }
            }
        }

        // ---- reduce P2 (fold bias2 pre-reduction, only lane s==g) -> wv2 ----
        float wv2[4];
#pragma unroll
        for (int g = 0; g < 4; g++) {
            float bb = (s == g) ? b2v : 0.0f;
            float2 f0 = unpk(a[2 * g + 0]);
            float2 f1 = unpk(a[2 * g + 1]);
            float v0 = f0.x + f0.y + bb;
            float v1 = f1.x + f1.y + bb;
            float snd = myrow ? v0 : v1;
            float own = myrow ? v1 : v0;
            float tt = own + __shfl_xor_sync(0xffffffffu, snd, 1);
            tt += __shfl_xor_sync(0xffffffffu, tt, 2);
            wv2[g] = tt;
        }

        // ---- reduce P1 (fold xp(t+1) pre-reduction) -> wv1 for next step ----
#pragma unroll
        for (int g = 0; g < 4; g++) {
            float2 f0 = unpk(b[2 * g + 0]);
            float2 f1 = unpk(b[2 * g + 1]);
            float v0 = f0.x + f0.y + ((s == g) ? xq0 : 0.0f);
            float v1 = f1.x + f1.y + ((s == g) ? xq1 : 0.0f);
            float snd = myrow ? v0 : v1;
            float own = myrow ? v1 : v0;
            float tt = own + __shfl_xor_sync(0xffffffffu, snd, 1);
            tt += __shfl_xor_sync(0xffffffffu, tt, 2);
            wv1[g] = tt;
        }

        // ---- cell-2 update + output head ----
        {
            float iv = sig_hw(wv2[0]), fv = sig_hw(wv2[1]);
            float gv = tanh_hw(wv2[2]), ov = sig_hw(wv2[3]);
            c2 = fv * c2 + iv * gv;
            float h2v = ov * tanh_hw(c2);
            if (s < 2) h2s[cur][s][q] = h2v;
            float p = wo * h2v;
            p += __shfl_xor_sync(0xffffffffu, p, 4);
            p += __shfl_xor_sync(0xffffffffu, p, 8);
            p += __shfl_xor_sync(0xffffffffu, p, 16);
            if ((tid & 31) < 2) red[(tid >> 5) * 2 + s] = p;
        }
        __syncthreads();              // B2: h2(cur) + red visible

        if (tid < 2) {
            float r = bo;
#pragma unroll
            for (int w = 0; w < 8; w++) r += red[w * 2 + tid];
            r = fminf(fmaxf(r, 0.0f), 1.0f);
            out[(size_t)(b0 + tid) * T_ + t] = r;
        }
    }
}

// ---------------- launch ----------------
extern "C" void kernel_launch(void* const* d_in, const int* in_sizes, int n_in,
                              void* d_out, int out_size) {
    const float* x    = (const float*)d_in[0];
    const float* Wih1 = (const float*)d_in[1];
    const float* Whh1 = (const float*)d_in[2];
    const float* bih1 = (const float*)d_in[3];
    const float* bhh1 = (const float*)d_in[4];
    const float* Wih2 = (const float*)d_in[5];
    const float* Whh2 = (const float*)d_in[6];
    const float* bih2 = (const float*)d_in[7];
    const float* bhh2 = (const float*)d_in[8];
    const float* Wout = (const float*)d_in[9];
    const float* bout = (const float*)d_in[10];
    float* out = (float*)d_out;

    xp_gemm<<<dim3((B_ * T_) / 64, G_ / 64), 256>>>(x, Wih1, bih1, bhh1);
    lstm_rec<<<128, 256>>>(Whh1, Wih2, Whh2, bih2, bhh2, Wout, bout, out);
    (void)in_sizes; (void)n_in; (void)out_size;
}